// round 1
// baseline (speedup 1.0000x reference)
#include <cuda_runtime.h>
#include <cstdint>

// Problem dims (fixed per reference setup_inputs)
#define B_    8
#define C_    128
#define N_    4096
#define M_    4096
#define OUT_  128

#define TM 64      // query rows per CTA
#define TN 128     // key tile
#define THREADS 256

// scratch (static device memory; allocation-free per harness rules)
__device__ float g_rn_in[B_ * N_];
__device__ float g_rn_tg[B_ * M_];
__device__ float g_agg[(size_t)B_ * M_ * C_];   // [b][m][c]

// ---------------------------------------------------------------------------
// Kernel 1: reciprocal L2 norms over C for a [B, C, L] tensor (L = 4096)
// which = 0 -> g_rn_in, which = 1 -> g_rn_tg
// ---------------------------------------------------------------------------
__global__ void rnorm_kernel(const float* __restrict__ x, int which) {
    int i = blockIdx.x * blockDim.x + threadIdx.x;   // over B*L
    if (i >= B_ * 4096) return;
    int b = i >> 12;          // / 4096
    int pos = i & 4095;
    const float* p = x + (size_t)b * C_ * 4096 + pos;
    float s = 0.f;
#pragma unroll 8
    for (int c = 0; c < C_; c++) {
        float v = p[(size_t)c * 4096];
        s += v * v;
    }
    float n = sqrtf(s);
    float r = 1.0f / fmaxf(n, 1e-12f);
    if (which) g_rn_tg[i] = r; else g_rn_in[i] = r;
}

// ---------------------------------------------------------------------------
// Kernel 2: fused flash-attention (cosine-sim adjacency + softmax + aggregate)
// grid = B * (M/TM) = 512, 256 threads (16x16)
// smem: q[64][128] | vt[128][132] | p[64][132]
// ---------------------------------------------------------------------------
#define VT_LD 132
#define P_LD  132

__global__ __launch_bounds__(THREADS, 1)
void attn_kernel(const float* __restrict__ input,
                 const float* __restrict__ tg) {
    extern __shared__ float smem[];
    float* q    = smem;                    // 64*128
    float* vt   = q + TM * C_;             // 128*132
    float* pbuf = vt + C_ * VT_LD;         // 64*132

    int bm = blockIdx.x;
    int b  = bm >> 6;                 // / (M/TM)=64
    int m0 = (bm & 63) * TM;
    int tid = threadIdx.x;
    int tx = tid & 15, ty = tid >> 4;

    const size_t inp_base = (size_t)b * C_ * N_;
    const size_t tg_base  = (size_t)b * C_ * M_;

    // load Q tile [TM][C]  (coalesced over m)
    for (int idx = tid; idx < TM * C_; idx += THREADS) {
        int i = idx & 63, c = idx >> 6;
        q[i * C_ + c] = tg[tg_base + (size_t)c * M_ + m0 + i];
    }

    float rq[4];
#pragma unroll
    for (int r = 0; r < 4; r++)
        rq[r] = g_rn_tg[b * M_ + m0 + 4 * ty + r];

    float m_run[4], l_run[4], acc[4][8];
#pragma unroll
    for (int r = 0; r < 4; r++) {
        m_run[r] = -1e30f;
        l_run[r] = 0.f;
#pragma unroll
        for (int j = 0; j < 8; j++) acc[r][j] = 0.f;
    }

    __syncthreads();

    for (int nt = 0; nt < N_ / TN; nt++) {
        int n0 = nt * TN;

        // load V tile (raw input) [C][TN] into vt with pad
        for (int idx = tid; idx < C_ * (TN / 4); idx += THREADS) {
            int j4 = idx & 31, c = idx >> 5;
            float4 v = *(const float4*)&input[inp_base + (size_t)c * N_ + n0 + 4 * j4];
            *(float4*)&vt[c * VT_LD + 4 * j4] = v;
        }
        __syncthreads();

        // ---- S = Q . K (raw dot, scaled later), micro-tile 4x8 ----
        float s[4][8];
#pragma unroll
        for (int r = 0; r < 4; r++)
#pragma unroll
            for (int j = 0; j < 8; j++) s[r][j] = 0.f;

        for (int c = 0; c < C_; c += 4) {
            float qreg[4][4];
#pragma unroll
            for (int r = 0; r < 4; r++) {
                float4 t = *(const float4*)&q[(4 * ty + r) * C_ + c];
                qreg[r][0] = t.x; qreg[r][1] = t.y; qreg[r][2] = t.z; qreg[r][3] = t.w;
            }
#pragma unroll
            for (int cc = 0; cc < 4; cc++) {
                float4 kA = *(const float4*)&vt[(c + cc) * VT_LD + 8 * tx];
                float4 kB = *(const float4*)&vt[(c + cc) * VT_LD + 8 * tx + 4];
                float kv[8] = {kA.x, kA.y, kA.z, kA.w, kB.x, kB.y, kB.z, kB.w};
#pragma unroll
                for (int r = 0; r < 4; r++)
#pragma unroll
                    for (int j = 0; j < 8; j++)
                        s[r][j] += qreg[r][cc] * kv[j];
            }
        }

        // scale by reciprocal norms
        float rnv[8];
#pragma unroll
        for (int j = 0; j < 8; j++)
            rnv[j] = g_rn_in[b * N_ + n0 + 8 * tx + j];
#pragma unroll
        for (int r = 0; r < 4; r++) {
            float rr = rq[r];
#pragma unroll
            for (int j = 0; j < 8; j++)
                s[r][j] *= rr * rnv[j];
        }

        // ---- online softmax (rows span 16 consecutive lanes) ----
#pragma unroll
        for (int r = 0; r < 4; r++) {
            float mx = s[r][0];
#pragma unroll
            for (int j = 1; j < 8; j++) mx = fmaxf(mx, s[r][j]);
#pragma unroll
            for (int o = 1; o < 16; o <<= 1)
                mx = fmaxf(mx, __shfl_xor_sync(0xffffffffu, mx, o));
            float m_new = fmaxf(m_run[r], mx);
            float corr = __expf(m_run[r] - m_new);
            m_run[r] = m_new;
            float ls = 0.f;
#pragma unroll
            for (int j = 0; j < 8; j++) {
                s[r][j] = __expf(s[r][j] - m_new);
                ls += s[r][j];
            }
#pragma unroll
            for (int o = 1; o < 16; o <<= 1)
                ls += __shfl_xor_sync(0xffffffffu, ls, o);
            l_run[r] = l_run[r] * corr + ls;
#pragma unroll
            for (int j = 0; j < 8; j++) acc[r][j] *= corr;
            // write P row
            *(float4*)&pbuf[(4 * ty + r) * P_LD + 8 * tx]     = make_float4(s[r][0], s[r][1], s[r][2], s[r][3]);
            *(float4*)&pbuf[(4 * ty + r) * P_LD + 8 * tx + 4] = make_float4(s[r][4], s[r][5], s[r][6], s[r][7]);
        }
        __syncthreads();

        // ---- acc += P . V^T   (contract over n; c ownership = tx + 16*j) ----
        for (int n = 0; n < TN; n += 4) {
            float vv[8][4];
#pragma unroll
            for (int j = 0; j < 8; j++) {
                float4 t = *(const float4*)&vt[(tx + 16 * j) * VT_LD + n];
                vv[j][0] = t.x; vv[j][1] = t.y; vv[j][2] = t.z; vv[j][3] = t.w;
            }
            float pp[4][4];
#pragma unroll
            for (int r = 0; r < 4; r++) {
                float4 t = *(const float4*)&pbuf[(4 * ty + r) * P_LD + n];
                pp[r][0] = t.x; pp[r][1] = t.y; pp[r][2] = t.z; pp[r][3] = t.w;
            }
#pragma unroll
            for (int nn = 0; nn < 4; nn++)
#pragma unroll
                for (int r = 0; r < 4; r++) {
                    float pv = pp[r][nn];
#pragma unroll
                    for (int j = 0; j < 8; j++)
                        acc[r][j] += pv * vv[j][nn];
                }
        }
        __syncthreads();
    }

    // finalize: agg[b][m][c] = acc / l
#pragma unroll
    for (int r = 0; r < 4; r++) {
        float inv_l = 1.0f / l_run[r];
        size_t base = ((size_t)(b * M_ + m0 + 4 * ty + r)) * C_;
#pragma unroll
        for (int j = 0; j < 8; j++)
            g_agg[base + tx + 16 * j] = acc[r][j] * inv_l;
    }
}

// ---------------------------------------------------------------------------
// Kernel 3: out[b][o][m] = BN(LeakyReLU(agg[b][m][:] . W[:,o]))
// grid = B * (M/TM) = 512, 256 threads
// smem: ws[128][128] | as[64][132] | sc[128] | bi[128]
// ---------------------------------------------------------------------------
#define A_LD 132
__global__ __launch_bounds__(THREADS, 1)
void epi_kernel(const float* __restrict__ w,
                const float* __restrict__ gamma,
                const float* __restrict__ beta,
                const float* __restrict__ rmean,
                const float* __restrict__ rvar,
                float* __restrict__ out) {
    extern __shared__ float smem[];
    float* ws = smem;                    // 128*128
    float* as = ws + C_ * OUT_;          // 64*132
    float* sc = as + TM * A_LD;          // 128
    float* bi = sc + OUT_;               // 128

    int bm = blockIdx.x;
    int b  = bm >> 6;
    int m0 = (bm & 63) * TM;
    int tid = threadIdx.x;
    int tx = tid & 15, ty = tid >> 4;

    // load W [C][OUT] (contiguous)
    for (int idx = tid; idx < C_ * OUT_ / 4; idx += THREADS)
        ((float4*)ws)[idx] = ((const float4*)w)[idx];

    // load agg tile
    for (int idx = tid; idx < TM * (C_ / 4); idx += THREADS) {
        int m = idx >> 5, c4 = idx & 31;
        float4 v = *(const float4*)&g_agg[((size_t)(b * M_ + m0 + m)) * C_ + 4 * c4];
        *(float4*)&as[m * A_LD + 4 * c4] = v;
    }

    if (tid < OUT_) {
        float s = rsqrtf(rvar[tid] + 1e-5f) * gamma[tid];
        sc[tid] = s;
        bi[tid] = beta[tid] - rmean[tid] * s;
    }
    __syncthreads();

    float acc[4][8];
#pragma unroll
    for (int r = 0; r < 4; r++)
#pragma unroll
        for (int j = 0; j < 8; j++) acc[r][j] = 0.f;

    for (int c = 0; c < C_; c += 4) {
        float areg[4][4];
#pragma unroll
        for (int r = 0; r < 4; r++) {
            float4 t = *(const float4*)&as[(4 * ty + r) * A_LD + c];
            areg[r][0] = t.x; areg[r][1] = t.y; areg[r][2] = t.z; areg[r][3] = t.w;
        }
#pragma unroll
        for (int cc = 0; cc < 4; cc++) {
            float4 wA = *(const float4*)&ws[(c + cc) * OUT_ + 8 * tx];
            float4 wB = *(const float4*)&ws[(c + cc) * OUT_ + 8 * tx + 4];
            float wv[8] = {wA.x, wA.y, wA.z, wA.w, wB.x, wB.y, wB.z, wB.w};
#pragma unroll
            for (int r = 0; r < 4; r++)
#pragma unroll
                for (int j = 0; j < 8; j++)
                    acc[r][j] += areg[r][cc] * wv[j];
        }
    }

#pragma unroll
    for (int r = 0; r < 4; r++) {
        int m = m0 + 4 * ty + r;
#pragma unroll
        for (int j = 0; j < 8; j++) {
            int o = 8 * tx + j;
            float z = acc[r][j];
            z = (z >= 0.f) ? z : 0.01f * z;
            out[((size_t)b * OUT_ + o) * M_ + m] = z * sc[o] + bi[o];
        }
    }
}

// ---------------------------------------------------------------------------
extern "C" void kernel_launch(void* const* d_in, const int* in_sizes, int n_in,
                              void* d_out, int out_size) {
    const float* input  = (const float*)d_in[0];
    const float* tg     = (const float*)d_in[1];
    const float* weight = (const float*)d_in[2];
    const float* gamma  = (const float*)d_in[3];
    const float* beta   = (const float*)d_in[4];
    const float* rmean  = (const float*)d_in[5];
    const float* rvar   = (const float*)d_in[6];
    float* out = (float*)d_out;

    const int attn_smem = (TM * C_ + C_ * VT_LD + TM * P_LD) * (int)sizeof(float);   // 134144
    const int epi_smem  = (C_ * OUT_ + TM * A_LD + 2 * OUT_) * (int)sizeof(float);   // 100352
    cudaFuncSetAttribute(attn_kernel, cudaFuncAttributeMaxDynamicSharedMemorySize, attn_smem);
    cudaFuncSetAttribute(epi_kernel,  cudaFuncAttributeMaxDynamicSharedMemorySize, epi_smem);

    // 1) reciprocal norms
    rnorm_kernel<<<(B_ * N_ + 255) / 256, 256>>>(input, 0);
    rnorm_kernel<<<(B_ * M_ + 255) / 256, 256>>>(tg, 1);

    // 2) fused attention
    attn_kernel<<<B_ * (M_ / TM), THREADS, attn_smem>>>(input, tg);

    // 3) projection + LeakyReLU + BatchNorm epilogue
    epi_kernel<<<B_ * (M_ / TM), THREADS, epi_smem>>>(weight, gamma, beta, rmean, rvar, out);
}

// round 5
// speedup vs baseline: 4.0191x; 4.0191x over previous
#include <cuda_runtime.h>
#include <cuda_bf16.h>
#include <cstdint>

#define B_    8
#define C_    128
#define N_    4096
#define M_    4096
#define OUT_  128
#define LOG2E 1.4426950408889634f

// single shared-mem declaration for the whole TU (nvcc requires consistency)
extern __shared__ char dyn_smem[];

// ---------------------------------------------------------------------------
// static device scratch (allocation-free)
// ---------------------------------------------------------------------------
__device__ __nv_bfloat16 g_qhi[(size_t)B_ * M_ * C_];   // [b][m][c] normalized*log2e hi
__device__ __nv_bfloat16 g_qlo[(size_t)B_ * M_ * C_];
__device__ __nv_bfloat16 g_khi[(size_t)B_ * N_ * C_];   // [b][n][c] normalized hi
__device__ __nv_bfloat16 g_klo[(size_t)B_ * N_ * C_];
__device__ __nv_bfloat16 g_vhi[(size_t)B_ * C_ * N_];   // [b][c][n] raw split
__device__ __nv_bfloat16 g_vlo[(size_t)B_ * C_ * N_];
__device__ float         g_agg[(size_t)B_ * M_ * C_];   // [b][m][c]

// ---------------------------------------------------------------------------
// helpers (base-ISA only: ldmatrix / mma.sync / cp.async)
// ---------------------------------------------------------------------------
__device__ __forceinline__ uint32_t smem_u32(const void* p) {
    uint32_t a;
    asm("{ .reg .u64 t; cvta.to.shared.u64 t, %1; cvt.u32.u64 %0, t; }" : "=r"(a) : "l"(p));
    return a;
}
__device__ __forceinline__ void ldsm4(uint32_t* r, uint32_t addr) {
    asm volatile("ldmatrix.sync.aligned.m8n8.x4.shared.b16 {%0,%1,%2,%3}, [%4];"
                 : "=r"(r[0]), "=r"(r[1]), "=r"(r[2]), "=r"(r[3]) : "r"(addr));
}
__device__ __forceinline__ void mma16816(float* d, const uint32_t* a, const uint32_t* b) {
    asm volatile("mma.sync.aligned.m16n8k16.row.col.f32.bf16.bf16.f32 "
                 "{%0,%1,%2,%3}, {%4,%5,%6,%7}, {%8,%9}, {%0,%1,%2,%3};"
                 : "+f"(d[0]), "+f"(d[1]), "+f"(d[2]), "+f"(d[3])
                 : "r"(a[0]), "r"(a[1]), "r"(a[2]), "r"(a[3]), "r"(b[0]), "r"(b[1]));
}
__device__ __forceinline__ void cpasync16(uint32_t saddr, const void* gaddr) {
    asm volatile("cp.async.cg.shared.global [%0], [%1], 16;" :: "r"(saddr), "l"(gaddr));
}
#define CP_COMMIT() asm volatile("cp.async.commit_group;" ::: "memory")
#define CP_WAIT1()  asm volatile("cp.async.wait_group 1;" ::: "memory")
__device__ __forceinline__ float fast_exp2(float x) {
    float r;
    asm("ex2.approx.ftz.f32 %0, %1;" : "=f"(r) : "f"(x));
    return r;
}
__device__ __forceinline__ uint32_t cvt_bf16x2(float up, float lo) {
    uint32_t d;
    asm("cvt.rn.bf16x2.f32 %0, %1, %2;" : "=r"(d) : "f"(up), "f"(lo));
    return d;
}
__device__ __forceinline__ uint32_t pack_bf2(__nv_bfloat16 a, __nv_bfloat16 b) {
    return (uint32_t)__bfloat16_as_ushort(a) | ((uint32_t)__bfloat16_as_ushort(b) << 16);
}

// ---------------------------------------------------------------------------
// prep: normalize over C, transpose to [b][l][c], bf16 hi/lo split
// ---------------------------------------------------------------------------
__global__ __launch_bounds__(256, 1)
void prep_qk(const float* __restrict__ x, __nv_bfloat16* __restrict__ hi_out,
             __nv_bfloat16* __restrict__ lo_out, float extra_scale) {
    float* t  = (float*)dyn_smem;              // [128][129]
    float* rn = t + 128 * 129;
    int blk = blockIdx.x;
    int b = blk >> 5, l0 = (blk & 31) * 128;
    int tid = threadIdx.x;
    const float* src = x + (size_t)b * C_ * 4096 + l0;
    for (int idx = tid; idx < 128 * 128; idx += 256) {
        int c = idx >> 7, l = idx & 127;
        t[c * 129 + l] = src[(size_t)c * 4096 + l];
    }
    __syncthreads();
    if (tid < 128) {
        float s = 0.f;
#pragma unroll 8
        for (int c = 0; c < 128; c++) { float v = t[c * 129 + tid]; s += v * v; }
        rn[tid] = extra_scale / fmaxf(sqrtf(s), 1e-12f);
    }
    __syncthreads();
    for (int idx = tid; idx < 128 * 128; idx += 256) {
        int l = idx >> 7, c = idx & 127;
        float v = t[c * 129 + l] * rn[l];
        __nv_bfloat16 h = __float2bfloat16(v);
        __nv_bfloat16 lo = __float2bfloat16(v - __bfloat162float(h));
        size_t o = ((size_t)b * 4096 + l0 + l) * C_ + c;
        hi_out[o] = h;
        lo_out[o] = lo;
    }
}

__global__ void prep_v(const float* __restrict__ x) {
    size_t i = (size_t)blockIdx.x * 256 + threadIdx.x;
    if (i >= (size_t)B_ * C_ * N_ / 4) return;
    float4 v = ((const float4*)x)[i];
    __nv_bfloat16 h0 = __float2bfloat16(v.x), h1 = __float2bfloat16(v.y);
    __nv_bfloat16 h2 = __float2bfloat16(v.z), h3 = __float2bfloat16(v.w);
    __nv_bfloat16 l0 = __float2bfloat16(v.x - __bfloat162float(h0));
    __nv_bfloat16 l1 = __float2bfloat16(v.y - __bfloat162float(h1));
    __nv_bfloat16 l2 = __float2bfloat16(v.z - __bfloat162float(h2));
    __nv_bfloat16 l3 = __float2bfloat16(v.w - __bfloat162float(h3));
    ((uint2*)g_vhi)[i] = make_uint2(pack_bf2(h0, h1), pack_bf2(h2, h3));
    ((uint2*)g_vlo)[i] = make_uint2(pack_bf2(l0, l1), pack_bf2(l2, l3));
}

// ---------------------------------------------------------------------------
// HMMA flash attention. grid = B*(M/128)=256, 256 threads (8 warps, 16 m/warp)
// N-tile 64, double-buffered K/V via cp.async.
// smem: Qhi 32K | Qlo 32K | 2 x { Khi 16K | Klo 16K | Vhi 16K | Vlo 16K }
// ---------------------------------------------------------------------------
#define SMQH 0
#define SMQL 32768
#define SMKV 65536
#define SM_BYTES 196608

__global__ __launch_bounds__(256, 1)
void attn_mma_kernel() {
    char* smc = dyn_smem;
    uint32_t sbase = smem_u32(smc);

    int tid = threadIdx.x;
    int w = tid >> 5, ln = tid & 31;
    int b  = blockIdx.x >> 5;
    int m0 = (blockIdx.x & 31) * 128;

    // ---- load Q tiles (plain, once) ----
    {
        const uint4* qh_g = (const uint4*)(g_qhi + ((size_t)b * M_ + m0) * C_);
        const uint4* ql_g = (const uint4*)(g_qlo + ((size_t)b * M_ + m0) * C_);
        for (int idx = tid; idx < 2048; idx += 256) {
            int row = idx >> 4, ch = idx & 15;
            uint32_t off = row * 256 + ((ch ^ (row & 7)) << 4);
            *(uint4*)(smc + SMQH + off) = qh_g[row * 16 + ch];
            *(uint4*)(smc + SMQL + off) = ql_g[row * 16 + ch];
        }
    }

    // cp.async tile loader: K [64n][128c] hi/lo + V [128c][64n] hi/lo
    auto issue_tiles = [&](int buf, int it) {
        int n0 = it * 64;
        uint32_t kb = sbase + SMKV + buf * 65536;
        const char* khg = (const char*)(g_khi + ((size_t)b * N_ + n0) * C_);
        const char* klg = (const char*)(g_klo + ((size_t)b * N_ + n0) * C_);
#pragma unroll
        for (int i = 0; i < 4; i++) {
            int idx = tid + i * 256;
            int row = idx >> 4, ch = idx & 15;
            uint32_t off = row * 256 + ((ch ^ (row & 7)) << 4);
            cpasync16(kb + off,          khg + row * 256 + ch * 16);
            cpasync16(kb + 16384 + off,  klg + row * 256 + ch * 16);
        }
        // V tile: 128 rows x 128 bytes = 8 chunks/row -> 1024 chunks
        const char* vhg = (const char*)(g_vhi + (size_t)b * C_ * N_ + n0);
        const char* vlg = (const char*)(g_vlo + (size_t)b * C_ * N_ + n0);
#pragma unroll
        for (int i = 0; i < 4; i++) {
            int idx = tid + i * 256;
            int row = idx >> 3, ch = idx & 7;
            uint32_t off = row * 128 + ((ch ^ (row & 7)) << 4);
            cpasync16(kb + 32768 + off, vhg + (size_t)row * 8192 + ch * 16);
            cpasync16(kb + 49152 + off, vlg + (size_t)row * 8192 + ch * 16);
        }
    };

    float oacc[16][4];
#pragma unroll
    for (int i = 0; i < 16; i++)
#pragma unroll
        for (int j = 0; j < 4; j++) oacc[i][j] = 0.f;
    float rs0 = 0.f, rs1 = 0.f;

    issue_tiles(0, 0);
    CP_COMMIT();

    for (int it = 0; it < 64; it++) {
        int buf = it & 1;
        __syncthreads();                       // prev reads of buf^1 done (+Q visible on it=0)
        if (it + 1 < 64) issue_tiles(buf ^ 1, it + 1);
        CP_COMMIT();
        CP_WAIT1();                            // tile `it` landed
        __syncthreads();

        uint32_t kbase = sbase + SMKV + buf * 65536;
        uint32_t vbase = kbase + 32768;

        // ---- S = Q.K^T (3-product compensated) ----
        float sacc[8][4];
#pragma unroll
        for (int i = 0; i < 8; i++)
#pragma unroll
            for (int j = 0; j < 4; j++) sacc[i][j] = 0.f;

#pragma unroll
        for (int ks = 0; ks < 8; ks++) {
            uint32_t qh[4], ql[4];
            {
                int r = 16 * w + (ln & 15);
                int ch = 2 * ks + (ln >> 4);
                uint32_t off = r * 256 + ((ch ^ (r & 7)) << 4);
                ldsm4(qh, sbase + SMQH + off);
                ldsm4(ql, sbase + SMQL + off);
            }
            uint32_t bh[4][4], bl[4][4];
#pragma unroll
            for (int p = 0; p < 4; p++) {
                int r = 16 * p + ((ln >> 4) << 3) + (ln & 7);
                int ch = 2 * ks + ((ln >> 3) & 1);
                uint32_t off = r * 256 + ((ch ^ (r & 7)) << 4);
                ldsm4(bh[p], kbase + off);
                ldsm4(bl[p], kbase + 16384 + off);
            }
#pragma unroll
            for (int p = 0; p < 4; p++) { mma16816(sacc[2*p], qh, bh[p]); mma16816(sacc[2*p+1], qh, bh[p]+2); }
#pragma unroll
            for (int p = 0; p < 4; p++) { mma16816(sacc[2*p], qh, bl[p]); mma16816(sacc[2*p+1], qh, bl[p]+2); }
#pragma unroll
            for (int p = 0; p < 4; p++) { mma16816(sacc[2*p], ql, bh[p]); mma16816(sacc[2*p+1], ql, bh[p]+2); }
        }

        // ---- P = exp2(S) (max-free: |s|<=log2e), split hi/lo, rowsum ----
        uint32_t phi[8][2], plo[8][2];
#pragma unroll
        for (int nb = 0; nb < 8; nb++) {
            float p0 = fast_exp2(sacc[nb][0]);
            float p1 = fast_exp2(sacc[nb][1]);
            float p2 = fast_exp2(sacc[nb][2]);
            float p3 = fast_exp2(sacc[nb][3]);
            rs0 += p0 + p1;
            rs1 += p2 + p3;
            uint32_t u0 = __float_as_uint(p0), u1 = __float_as_uint(p1);
            uint32_t u2 = __float_as_uint(p2), u3 = __float_as_uint(p3);
            phi[nb][0] = __byte_perm(u0, u1, 0x7632);
            phi[nb][1] = __byte_perm(u2, u3, 0x7632);
            float q0 = p0 - __uint_as_float(u0 & 0xFFFF0000u);
            float q1 = p1 - __uint_as_float(u1 & 0xFFFF0000u);
            float q2 = p2 - __uint_as_float(u2 & 0xFFFF0000u);
            float q3 = p3 - __uint_as_float(u3 & 0xFFFF0000u);
            plo[nb][0] = cvt_bf16x2(q1, q0);
            plo[nb][1] = cvt_bf16x2(q3, q2);
        }

        // ---- O += P.V^T (S-accum fragments reused directly as A-frags) ----
#pragma unroll
        for (int kn = 0; kn < 4; kn++) {
            uint32_t ah[4] = {phi[2*kn][0], phi[2*kn][1], phi[2*kn+1][0], phi[2*kn+1][1]};
            uint32_t al[4] = {plo[2*kn][0], plo[2*kn][1], plo[2*kn+1][0], plo[2*kn+1][1]};
#pragma unroll
            for (int g = 0; g < 2; g++) {
                uint32_t vh[4][4], vl[4][4];
#pragma unroll
                for (int p = 0; p < 4; p++) {
                    int r = 16 * (4 * g + p) + ((ln >> 4) << 3) + (ln & 7);
                    int ch = 2 * kn + ((ln >> 3) & 1);
                    uint32_t off = r * 128 + ((ch ^ (r & 7)) << 4);
                    ldsm4(vh[p], vbase + off);
                    ldsm4(vl[p], vbase + 16384 + off);
                }
#pragma unroll
                for (int p = 0; p < 4; p++) { int cb = 8*g + 2*p; mma16816(oacc[cb], ah, vh[p]); mma16816(oacc[cb+1], ah, vh[p]+2); }
#pragma unroll
                for (int p = 0; p < 4; p++) { int cb = 8*g + 2*p; mma16816(oacc[cb], ah, vl[p]); mma16816(oacc[cb+1], ah, vl[p]+2); }
#pragma unroll
                for (int p = 0; p < 4; p++) { int cb = 8*g + 2*p; mma16816(oacc[cb], al, vh[p]); mma16816(oacc[cb+1], al, vh[p]+2); }
            }
        }
    }

    // ---- finalize: divide by row sums, store [b][m][c] ----
    rs0 += __shfl_xor_sync(0xffffffffu, rs0, 1);
    rs0 += __shfl_xor_sync(0xffffffffu, rs0, 2);
    rs1 += __shfl_xor_sync(0xffffffffu, rs1, 1);
    rs1 += __shfl_xor_sync(0xffffffffu, rs1, 2);
    float inv0 = 1.0f / rs0, inv1 = 1.0f / rs1;

    float* dst = g_agg + ((size_t)(b * M_ + m0 + 16 * w + (ln >> 2))) * C_ + 2 * (ln & 3);
#pragma unroll
    for (int cb = 0; cb < 16; cb++) {
        *(float2*)(dst + 8 * cb)          = make_float2(oacc[cb][0] * inv0, oacc[cb][1] * inv0);
        *(float2*)(dst + 8 * C_ + 8 * cb) = make_float2(oacc[cb][2] * inv1, oacc[cb][3] * inv1);
    }
}

// ---------------------------------------------------------------------------
// epilogue: out[b][o][m] = BN(LeakyReLU(agg[b][m][:] . W[:,o]))
// ---------------------------------------------------------------------------
#define TM 64
#define A_LD 132
#define THREADS 256
__global__ __launch_bounds__(THREADS, 1)
void epi_kernel(const float* __restrict__ w,
                const float* __restrict__ gamma,
                const float* __restrict__ beta,
                const float* __restrict__ rmean,
                const float* __restrict__ rvar,
                float* __restrict__ out) {
    float* ws = (float*)dyn_smem;        // 128*128
    float* as = ws + C_ * OUT_;
    float* sc = as + TM * A_LD;
    float* bi = sc + OUT_;

    int bm = blockIdx.x;
    int b  = bm >> 6;
    int m0 = (bm & 63) * TM;
    int tid = threadIdx.x;
    int tx = tid & 15, ty = tid >> 4;

    for (int idx = tid; idx < C_ * OUT_ / 4; idx += THREADS)
        ((float4*)ws)[idx] = ((const float4*)w)[idx];
    for (int idx = tid; idx < TM * (C_ / 4); idx += THREADS) {
        int m = idx >> 5, c4 = idx & 31;
        float4 v = *(const float4*)&g_agg[((size_t)(b * M_ + m0 + m)) * C_ + 4 * c4];
        *(float4*)&as[m * A_LD + 4 * c4] = v;
    }
    if (tid < OUT_) {
        float s = rsqrtf(rvar[tid] + 1e-5f) * gamma[tid];
        sc[tid] = s;
        bi[tid] = beta[tid] - rmean[tid] * s;
    }
    __syncthreads();

    float acc[4][8];
#pragma unroll
    for (int r = 0; r < 4; r++)
#pragma unroll
        for (int j = 0; j < 8; j++) acc[r][j] = 0.f;

    for (int c = 0; c < C_; c += 4) {
        float areg[4][4];
#pragma unroll
        for (int r = 0; r < 4; r++) {
            float4 t = *(const float4*)&as[(4 * ty + r) * A_LD + c];
            areg[r][0] = t.x; areg[r][1] = t.y; areg[r][2] = t.z; areg[r][3] = t.w;
        }
#pragma unroll
        for (int cc = 0; cc < 4; cc++) {
            float4 wA = *(const float4*)&ws[(c + cc) * OUT_ + 8 * tx];
            float4 wB = *(const float4*)&ws[(c + cc) * OUT_ + 8 * tx + 4];
            float wv[8] = {wA.x, wA.y, wA.z, wA.w, wB.x, wB.y, wB.z, wB.w};
#pragma unroll
            for (int r = 0; r < 4; r++)
#pragma unroll
                for (int j = 0; j < 8; j++)
                    acc[r][j] += areg[r][cc] * wv[j];
        }
    }
#pragma unroll
    for (int r = 0; r < 4; r++) {
        int m = m0 + 4 * ty + r;
#pragma unroll
        for (int j = 0; j < 8; j++) {
            int o = 8 * tx + j;
            float z = acc[r][j];
            z = (z >= 0.f) ? z : 0.01f * z;
            out[((size_t)b * OUT_ + o) * M_ + m] = z * sc[o] + bi[o];
        }
    }
}

// ---------------------------------------------------------------------------
extern "C" void kernel_launch(void* const* d_in, const int* in_sizes, int n_in,
                              void* d_out, int out_size) {
    const float* input  = (const float*)d_in[0];
    const float* tg     = (const float*)d_in[1];
    const float* weight = (const float*)d_in[2];
    const float* gamma  = (const float*)d_in[3];
    const float* beta   = (const float*)d_in[4];
    const float* rmean  = (const float*)d_in[5];
    const float* rvar   = (const float*)d_in[6];
    float* out = (float*)d_out;

    __nv_bfloat16 *p_qhi, *p_qlo, *p_khi, *p_klo;
    cudaGetSymbolAddress((void**)&p_qhi, g_qhi);
    cudaGetSymbolAddress((void**)&p_qlo, g_qlo);
    cudaGetSymbolAddress((void**)&p_khi, g_khi);
    cudaGetSymbolAddress((void**)&p_klo, g_klo);

    const int prep_smem = (128 * 129 + 128) * (int)sizeof(float);
    const int epi_smem  = (C_ * OUT_ + TM * A_LD + 2 * OUT_) * (int)sizeof(float);
    cudaFuncSetAttribute(prep_qk, cudaFuncAttributeMaxDynamicSharedMemorySize, prep_smem);
    cudaFuncSetAttribute(attn_mma_kernel, cudaFuncAttributeMaxDynamicSharedMemorySize, SM_BYTES);
    cudaFuncSetAttribute(epi_kernel, cudaFuncAttributeMaxDynamicSharedMemorySize, epi_smem);

    prep_qk<<<B_ * (M_ / 128), 256, prep_smem>>>(tg,    p_qhi, p_qlo, LOG2E);
    prep_qk<<<B_ * (N_ / 128), 256, prep_smem>>>(input, p_khi, p_klo, 1.0f);
    prep_v<<<(B_ * C_ * N_ / 4 + 255) / 256, 256>>>(input);

    attn_mma_kernel<<<B_ * (M_ / 128), 256, SM_BYTES>>>();

    epi_kernel<<<B_ * (M_ / 64), THREADS, epi_smem>>>(weight, gamma, beta, rmean, rvar, out);
}

// round 6
// speedup vs baseline: 5.2829x; 1.3144x over previous
#include <cuda_runtime.h>
#include <cuda_fp16.h>
#include <cstdint>

#define B_    8
#define C_    128
#define N_    4096
#define M_    4096
#define OUT_  128
#define LOG2E 1.4426950408889634f

// single shared-mem declaration for the whole TU (nvcc requires consistency)
extern __shared__ char dyn_smem[];

// ---------------------------------------------------------------------------
// static device scratch (allocation-free)
// ---------------------------------------------------------------------------
__device__ __half g_qh[(size_t)B_ * M_ * C_];   // [b][m][c] normalized*log2e (fp16, single rounding)
__device__ __half g_kh[(size_t)B_ * N_ * C_];   // [b][n][c] normalized hi
__device__ __half g_kl[(size_t)B_ * N_ * C_];   // residual
__device__ __half g_vh[(size_t)B_ * C_ * N_];   // [b][c][n] raw hi
__device__ __half g_vl[(size_t)B_ * C_ * N_];   // residual
__device__ float  g_agg[(size_t)B_ * M_ * C_];  // [b][m][c]

// ---------------------------------------------------------------------------
// helpers (base-ISA only: ldmatrix / mma.sync / cp.async)
// ---------------------------------------------------------------------------
__device__ __forceinline__ uint32_t smem_u32(const void* p) {
    uint32_t a;
    asm("{ .reg .u64 t; cvta.to.shared.u64 t, %1; cvt.u32.u64 %0, t; }" : "=r"(a) : "l"(p));
    return a;
}
__device__ __forceinline__ void ldsm4(uint32_t* r, uint32_t addr) {
    asm volatile("ldmatrix.sync.aligned.m8n8.x4.shared.b16 {%0,%1,%2,%3}, [%4];"
                 : "=r"(r[0]), "=r"(r[1]), "=r"(r[2]), "=r"(r[3]) : "r"(addr));
}
__device__ __forceinline__ void mma16816(float* d, const uint32_t* a, const uint32_t* b) {
    asm volatile("mma.sync.aligned.m16n8k16.row.col.f32.f16.f16.f32 "
                 "{%0,%1,%2,%3}, {%4,%5,%6,%7}, {%8,%9}, {%0,%1,%2,%3};"
                 : "+f"(d[0]), "+f"(d[1]), "+f"(d[2]), "+f"(d[3])
                 : "r"(a[0]), "r"(a[1]), "r"(a[2]), "r"(a[3]), "r"(b[0]), "r"(b[1]));
}
__device__ __forceinline__ void cpasync16(uint32_t saddr, const void* gaddr) {
    asm volatile("cp.async.cg.shared.global [%0], [%1], 16;" :: "r"(saddr), "l"(gaddr));
}
#define CP_COMMIT() asm volatile("cp.async.commit_group;" ::: "memory")
#define CP_WAIT1()  asm volatile("cp.async.wait_group 1;" ::: "memory")
__device__ __forceinline__ float fast_exp2(float x) {
    float r;
    asm("ex2.approx.ftz.f32 %0, %1;" : "=f"(r) : "f"(x));
    return r;
}
__device__ __forceinline__ uint32_t pack_h2(float lo, float hi) {
    __half2 h = __floats2half2_rn(lo, hi);   // lo -> low 16 bits
    return *(uint32_t*)&h;
}

// ---------------------------------------------------------------------------
// prep: normalize over C, transpose to [b][l][c], fp16 (hi [+ residual lo])
// ---------------------------------------------------------------------------
__global__ __launch_bounds__(256, 1)
void prep_qk(const float* __restrict__ x, __half* __restrict__ hi_out,
             __half* __restrict__ lo_out, float extra_scale) {
    float* t  = (float*)dyn_smem;              // [128][129]
    float* rn = t + 128 * 129;
    int blk = blockIdx.x;
    int b = blk >> 5, l0 = (blk & 31) * 128;
    int tid = threadIdx.x;
    const float* src = x + (size_t)b * C_ * 4096 + l0;
    for (int idx = tid; idx < 128 * 128; idx += 256) {
        int c = idx >> 7, l = idx & 127;
        t[c * 129 + l] = src[(size_t)c * 4096 + l];
    }
    __syncthreads();
    if (tid < 128) {
        float s = 0.f;
#pragma unroll 8
        for (int c = 0; c < 128; c++) { float v = t[c * 129 + tid]; s += v * v; }
        rn[tid] = extra_scale / fmaxf(sqrtf(s), 1e-12f);
    }
    __syncthreads();
    for (int idx = tid; idx < 128 * 128; idx += 256) {
        int l = idx >> 7, c = idx & 127;
        float v = t[c * 129 + l] * rn[l];
        __half h = __float2half_rn(v);
        size_t o = ((size_t)b * 4096 + l0 + l) * C_ + c;
        hi_out[o] = h;
        if (lo_out) lo_out[o] = __float2half_rn(v - __half2float(h));
    }
}

__global__ void prep_v(const float* __restrict__ x) {
    size_t i = (size_t)blockIdx.x * 256 + threadIdx.x;
    if (i >= (size_t)B_ * C_ * N_ / 4) return;
    float4 v = ((const float4*)x)[i];
    __half h0 = __float2half_rn(v.x), h1 = __float2half_rn(v.y);
    __half h2 = __float2half_rn(v.z), h3 = __float2half_rn(v.w);
    ((uint2*)g_vh)[i] = make_uint2(pack_h2(v.x, v.y) * 0u + ((uint32_t)*(unsigned short*)&h0 | ((uint32_t)*(unsigned short*)&h1 << 16)),
                                   ((uint32_t)*(unsigned short*)&h2 | ((uint32_t)*(unsigned short*)&h3 << 16)));
    ((uint2*)g_vl)[i] = make_uint2(pack_h2(v.x - __half2float(h0), v.y - __half2float(h1)),
                                   pack_h2(v.z - __half2float(h2), v.w - __half2float(h3)));
}

// ---------------------------------------------------------------------------
// HMMA fp16 flash attention. grid = B*(M/128)=256, 256 threads (8 warps)
// N-tile 64, double-buffered K/V via cp.async.
// smem: Qh 32K | 2 x { Kh 16K | Kl 16K | Vh 16K | Vl 16K }
// ---------------------------------------------------------------------------
#define SMQH 0
#define SMKV 32768
#define SM_BYTES 163840

__global__ __launch_bounds__(256, 1)
void attn_mma_kernel() {
    char* smc = dyn_smem;
    uint32_t sbase = smem_u32(smc);

    int tid = threadIdx.x;
    int w = tid >> 5, ln = tid & 31;
    int b  = blockIdx.x >> 5;
    int m0 = (blockIdx.x & 31) * 128;

    // ---- load Q tile (once) ----
    {
        const uint4* qh_g = (const uint4*)(g_qh + ((size_t)b * M_ + m0) * C_);
        for (int idx = tid; idx < 2048; idx += 256) {
            int row = idx >> 4, ch = idx & 15;
            uint32_t off = row * 256 + ((ch ^ (row & 7)) << 4);
            *(uint4*)(smc + SMQH + off) = qh_g[row * 16 + ch];
        }
    }

    // cp.async tile loader: K [64n][128c] hi/lo + V [128c][64n] hi/lo
    auto issue_tiles = [&](int buf, int it) {
        int n0 = it * 64;
        uint32_t kb = sbase + SMKV + buf * 65536;
        const char* khg = (const char*)(g_kh + ((size_t)b * N_ + n0) * C_);
        const char* klg = (const char*)(g_kl + ((size_t)b * N_ + n0) * C_);
#pragma unroll
        for (int i = 0; i < 4; i++) {
            int idx = tid + i * 256;
            int row = idx >> 4, ch = idx & 15;
            uint32_t off = row * 256 + ((ch ^ (row & 7)) << 4);
            cpasync16(kb + off,          khg + row * 256 + ch * 16);
            cpasync16(kb + 16384 + off,  klg + row * 256 + ch * 16);
        }
        // V tile: 128 rows x 128 bytes = 8 chunks/row -> 1024 chunks
        const char* vhg = (const char*)(g_vh + (size_t)b * C_ * N_ + n0);
        const char* vlg = (const char*)(g_vl + (size_t)b * C_ * N_ + n0);
#pragma unroll
        for (int i = 0; i < 4; i++) {
            int idx = tid + i * 256;
            int row = idx >> 3, ch = idx & 7;
            uint32_t off = row * 128 + ((ch ^ (row & 7)) << 4);
            cpasync16(kb + 32768 + off, vhg + (size_t)row * 8192 + ch * 16);
            cpasync16(kb + 49152 + off, vlg + (size_t)row * 8192 + ch * 16);
        }
    };

    float oacc[16][4];
#pragma unroll
    for (int i = 0; i < 16; i++)
#pragma unroll
        for (int j = 0; j < 4; j++) oacc[i][j] = 0.f;
    float rs0 = 0.f, rs1 = 0.f;

    issue_tiles(0, 0);
    CP_COMMIT();

    for (int it = 0; it < 64; it++) {
        int buf = it & 1;
        __syncthreads();                       // prev reads of buf^1 done (+Q visible on it=0)
        if (it + 1 < 64) issue_tiles(buf ^ 1, it + 1);
        CP_COMMIT();
        CP_WAIT1();                            // tile `it` landed
        __syncthreads();

        uint32_t kbase = sbase + SMKV + buf * 65536;
        uint32_t vbase = kbase + 32768;

        // ---- S = Q.K^T  (Qh*Kh + Qh*Kl) ----
        float sacc[8][4];
#pragma unroll
        for (int i = 0; i < 8; i++)
#pragma unroll
            for (int j = 0; j < 4; j++) sacc[i][j] = 0.f;

#pragma unroll
        for (int ks = 0; ks < 8; ks++) {
            uint32_t qh[4];
            {
                int r = 16 * w + (ln & 15);
                int ch = 2 * ks + (ln >> 4);
                uint32_t off = r * 256 + ((ch ^ (r & 7)) << 4);
                ldsm4(qh, sbase + SMQH + off);
            }
            uint32_t bh[4][4], bl[4][4];
#pragma unroll
            for (int p = 0; p < 4; p++) {
                int r = 16 * p + ((ln >> 4) << 3) + (ln & 7);
                int ch = 2 * ks + ((ln >> 3) & 1);
                uint32_t off = r * 256 + ((ch ^ (r & 7)) << 4);
                ldsm4(bh[p], kbase + off);
                ldsm4(bl[p], kbase + 16384 + off);
            }
#pragma unroll
            for (int p = 0; p < 4; p++) { mma16816(sacc[2*p], qh, bh[p]); mma16816(sacc[2*p+1], qh, bh[p]+2); }
#pragma unroll
            for (int p = 0; p < 4; p++) { mma16816(sacc[2*p], qh, bl[p]); mma16816(sacc[2*p+1], qh, bl[p]+2); }
        }

        // ---- P = exp2(S) (max-free: scores bounded), fp16 pack, rowsum ----
        uint32_t phi[8][2];
#pragma unroll
        for (int nb = 0; nb < 8; nb++) {
            float p0 = fast_exp2(sacc[nb][0]);
            float p1 = fast_exp2(sacc[nb][1]);
            float p2 = fast_exp2(sacc[nb][2]);
            float p3 = fast_exp2(sacc[nb][3]);
            rs0 += p0 + p1;
            rs1 += p2 + p3;
            phi[nb][0] = pack_h2(p0, p1);
            phi[nb][1] = pack_h2(p2, p3);
        }

        // ---- O += P.V^T  (Ph*Vh + Ph*Vl) ----
#pragma unroll
        for (int kn = 0; kn < 4; kn++) {
            uint32_t ah[4] = {phi[2*kn][0], phi[2*kn][1], phi[2*kn+1][0], phi[2*kn+1][1]};
#pragma unroll
            for (int g = 0; g < 2; g++) {
                uint32_t vh[4][4], vl[4][4];
#pragma unroll
                for (int p = 0; p < 4; p++) {
                    int r = 16 * (4 * g + p) + ((ln >> 4) << 3) + (ln & 7);
                    int ch = 2 * kn + ((ln >> 3) & 1);
                    uint32_t off = r * 128 + ((ch ^ (r & 7)) << 4);
                    ldsm4(vh[p], vbase + off);
                    ldsm4(vl[p], vbase + 16384 + off);
                }
#pragma unroll
                for (int p = 0; p < 4; p++) { int cb = 8*g + 2*p; mma16816(oacc[cb], ah, vh[p]); mma16816(oacc[cb+1], ah, vh[p]+2); }
#pragma unroll
                for (int p = 0; p < 4; p++) { int cb = 8*g + 2*p; mma16816(oacc[cb], ah, vl[p]); mma16816(oacc[cb+1], ah, vl[p]+2); }
            }
        }
    }

    // ---- finalize: divide by row sums, store [b][m][c] ----
    rs0 += __shfl_xor_sync(0xffffffffu, rs0, 1);
    rs0 += __shfl_xor_sync(0xffffffffu, rs0, 2);
    rs1 += __shfl_xor_sync(0xffffffffu, rs1, 1);
    rs1 += __shfl_xor_sync(0xffffffffu, rs1, 2);
    float inv0 = 1.0f / rs0, inv1 = 1.0f / rs1;

    float* dst = g_agg + ((size_t)(b * M_ + m0 + 16 * w + (ln >> 2))) * C_ + 2 * (ln & 3);
#pragma unroll
    for (int cb = 0; cb < 16; cb++) {
        *(float2*)(dst + 8 * cb)          = make_float2(oacc[cb][0] * inv0, oacc[cb][1] * inv0);
        *(float2*)(dst + 8 * C_ + 8 * cb) = make_float2(oacc[cb][2] * inv1, oacc[cb][3] * inv1);
    }
}

// ---------------------------------------------------------------------------
// epilogue: out[b][o][m] = BN(LeakyReLU(agg[b][m][:] . W[:,o]))
// OUT split in halves per CTA for occupancy (3 CTAs/SM).
// grid = B*(M/64)*2 = 1024, 256 threads (16x16), microtile 4m x 4o
// ---------------------------------------------------------------------------
#define TM 64
#define A_LD 132
#define OH 64
#define THREADS 256
__global__ __launch_bounds__(THREADS)
void epi_kernel(const float* __restrict__ w,
                const float* __restrict__ gamma,
                const float* __restrict__ beta,
                const float* __restrict__ rmean,
                const float* __restrict__ rvar,
                float* __restrict__ out) {
    float* ws = (float*)dyn_smem;        // [128][64]
    float* as = ws + C_ * OH;            // [64][132]
    float* sc = as + TM * A_LD;          // [64]
    float* bi = sc + OH;                 // [64]

    int bm = blockIdx.x;
    int half = bm & 1;
    int rest = bm >> 1;
    int b  = rest >> 6;
    int m0 = (rest & 63) * TM;
    int o0 = half * OH;
    int tid = threadIdx.x;
    int tx = tid & 15, ty = tid >> 4;

    // load W half: [c][o0..o0+63]
    for (int idx = tid; idx < C_ * (OH / 4); idx += THREADS) {
        int c = idx >> 4, o4 = idx & 15;
        *(float4*)&ws[c * OH + 4 * o4] = *(const float4*)&w[c * OUT_ + o0 + 4 * o4];
    }
    for (int idx = tid; idx < TM * (C_ / 4); idx += THREADS) {
        int m = idx >> 5, c4 = idx & 31;
        float4 v = *(const float4*)&g_agg[((size_t)(b * M_ + m0 + m)) * C_ + 4 * c4];
        *(float4*)&as[m * A_LD + 4 * c4] = v;
    }
    if (tid < OH) {
        int o = o0 + tid;
        float s = rsqrtf(rvar[o] + 1e-5f) * gamma[o];
        sc[tid] = s;
        bi[tid] = beta[o] - rmean[o] * s;
    }
    __syncthreads();

    float acc[4][4];
#pragma unroll
    for (int r = 0; r < 4; r++)
#pragma unroll
        for (int j = 0; j < 4; j++) acc[r][j] = 0.f;

    for (int c = 0; c < C_; c += 4) {
        float areg[4][4];
#pragma unroll
        for (int r = 0; r < 4; r++) {
            float4 t = *(const float4*)&as[(4 * ty + r) * A_LD + c];
            areg[r][0] = t.x; areg[r][1] = t.y; areg[r][2] = t.z; areg[r][3] = t.w;
        }
#pragma unroll
        for (int cc = 0; cc < 4; cc++) {
            float4 wv = *(const float4*)&ws[(c + cc) * OH + 4 * tx];
            float wa[4] = {wv.x, wv.y, wv.z, wv.w};
#pragma unroll
            for (int r = 0; r < 4; r++)
#pragma unroll
                for (int j = 0; j < 4; j++)
                    acc[r][j] += areg[r][cc] * wa[j];
        }
    }
#pragma unroll
    for (int r = 0; r < 4; r++) {
        int m = m0 + 4 * ty + r;
#pragma unroll
        for (int j = 0; j < 4; j++) {
            int ol = 4 * tx + j;
            float z = acc[r][j];
            z = (z >= 0.f) ? z : 0.01f * z;
            out[((size_t)b * OUT_ + o0 + ol) * M_ + m] = z * sc[ol] + bi[ol];
        }
    }
}

// ---------------------------------------------------------------------------
extern "C" void kernel_launch(void* const* d_in, const int* in_sizes, int n_in,
                              void* d_out, int out_size) {
    const float* input  = (const float*)d_in[0];
    const float* tg     = (const float*)d_in[1];
    const float* weight = (const float*)d_in[2];
    const float* gamma  = (const float*)d_in[3];
    const float* beta   = (const float*)d_in[4];
    const float* rmean  = (const float*)d_in[5];
    const float* rvar   = (const float*)d_in[6];
    float* out = (float*)d_out;

    __half *p_qh, *p_kh, *p_kl;
    cudaGetSymbolAddress((void**)&p_qh, g_qh);
    cudaGetSymbolAddress((void**)&p_kh, g_kh);
    cudaGetSymbolAddress((void**)&p_kl, g_kl);

    const int prep_smem = (128 * 129 + 128) * (int)sizeof(float);
    const int epi_smem  = (C_ * OH + TM * A_LD + 2 * OH) * (int)sizeof(float);
    cudaFuncSetAttribute(prep_qk, cudaFuncAttributeMaxDynamicSharedMemorySize, prep_smem);
    cudaFuncSetAttribute(attn_mma_kernel, cudaFuncAttributeMaxDynamicSharedMemorySize, SM_BYTES);
    cudaFuncSetAttribute(epi_kernel, cudaFuncAttributeMaxDynamicSharedMemorySize, epi_smem);

    prep_qk<<<B_ * (M_ / 128), 256, prep_smem>>>(tg,    p_qh, nullptr, LOG2E);
    prep_qk<<<B_ * (N_ / 128), 256, prep_smem>>>(input, p_kh, p_kl, 1.0f);
    prep_v<<<(B_ * C_ * N_ / 4 + 255) / 256, 256>>>(input);

    attn_mma_kernel<<<B_ * (M_ / 128), 256, SM_BYTES>>>();

    epi_kernel<<<B_ * (M_ / 64) * 2, THREADS, epi_smem>>>(weight, gamma, beta, rmean, rvar, out);
}